// round 2
// baseline (speedup 1.0000x reference)
#include <cuda_runtime.h>
#include <cuda_bf16.h>

#define VOCAB 256
#define CHARS 20
#define ROWS_PER_BLOCK 8
#define THREADS 256
// float4 stores of output per block: 8*256/4 = 512 -> 2 per thread
#define VEC_ITERS ((ROWS_PER_BLOCK * VOCAB / 4) / THREADS)

__global__ void __launch_bounds__(THREADS) fofe_direct_kernel(
    const int* __restrict__ char_ids,
    const float* __restrict__ forgetting_factor,
    float* __restrict__ out)
{
    __shared__ float pw_s[CHARS];

    const int t = threadIdx.x;
    const int row0 = blockIdx.x * ROWS_PER_BLOCK;
    float* block_out = out + (size_t)row0 * VOCAB;

    // Phase A: zero this block's 8 output rows directly in global memory
    // (fully coalesced float4 streaming stores; lines land dirty in L2)
    float4* o4 = reinterpret_cast<float4*>(block_out);
    const float4 z = make_float4(0.f, 0.f, 0.f, 0.f);
#pragma unroll
    for (int i = 0; i < VEC_ITERS; ++i)
        o4[t + i * THREADS] = z;

    // powers alpha^(CHARS-1-k) for k = 0..CHARS-1 (computed concurrently)
    if (t < CHARS) {
        const float alpha = __ldg(forgetting_factor);
        float p = 1.f;
        const int e = (CHARS - 1) - t;
        for (int i = 0; i < e; ++i) p *= alpha;
        pw_s[t] = p;
    }

    // fence.cta + barrier: block-private rows, zeros visible to our atomics
    __syncthreads();

    // Phase B: scatter 8 rows * 20 chars = 160 contributions via global
    // atomicAdd -> REDG.ADD.F32, RMW in L2 on the just-written lines.
    if (t < ROWS_PER_BLOCK * CHARS) {
        const int r = t / CHARS;          // local row 0..7
        const int k = t - r * CHARS;      // char position 0..19
        const int id = __ldg(char_ids + (size_t)(row0 + r) * CHARS + k);
        atomicAdd(block_out + r * VOCAB + id, pw_s[k]);
    }
}

extern "C" void kernel_launch(void* const* d_in, const int* in_sizes, int n_in,
                              void* d_out, int out_size) {
    const int* char_ids;
    const float* ff;
    if (in_sizes[0] > in_sizes[1]) {
        char_ids = (const int*)d_in[0];
        ff = (const float*)d_in[1];
    } else {
        char_ids = (const int*)d_in[1];
        ff = (const float*)d_in[0];
    }
    float* out = (float*)d_out;

    const int n_rows = out_size / VOCAB;            // 131072
    const int n_blocks = n_rows / ROWS_PER_BLOCK;   // 16384

    fofe_direct_kernel<<<n_blocks, THREADS>>>(char_ids, ff, out);
}

// round 3
// speedup vs baseline: 1.0959x; 1.0959x over previous
#include <cuda_runtime.h>
#include <cuda_bf16.h>
#include <cstdint>

#define VOCAB 256
#define CHARS 20
#define ROWS_PER_BLOCK 16
#define THREADS 256
#define HIST_FLOATS (ROWS_PER_BLOCK * VOCAB)          // 4096
#define HIST_BYTES  (HIST_FLOATS * 4)                 // 16384
#define ZERO_ITERS  ((HIST_FLOATS / 4) / THREADS)     // 4 float4 per thread
#define TASKS       (ROWS_PER_BLOCK * CHARS)          // 320

__device__ __forceinline__ uint32_t smem_u32(const void* p) {
    uint32_t a;
    asm("{ .reg .u64 t; cvta.to.shared.u64 t, %1; cvt.u32.u64 %0, t; }"
        : "=r"(a) : "l"(p));
    return a;
}

__global__ void __launch_bounds__(THREADS) fofe_tma_kernel(
    const int* __restrict__ char_ids,
    const float* __restrict__ forgetting_factor,
    float* __restrict__ out)
{
    __shared__ __align__(128) float hist[HIST_FLOATS];
    __shared__ float pw_s[CHARS];

    const int t = threadIdx.x;
    const int row0 = blockIdx.x * ROWS_PER_BLOCK;
    float* block_out = out + (size_t)row0 * VOCAB;

    // Phase A: zero the smem histograms (STS.128, conflict-free)
    float4* h4 = reinterpret_cast<float4*>(hist);
    const float4 z = make_float4(0.f, 0.f, 0.f, 0.f);
#pragma unroll
    for (int i = 0; i < ZERO_ITERS; ++i)
        h4[t + i * THREADS] = z;

    // powers alpha^(CHARS-1-k)
    if (t < CHARS) {
        const float alpha = __ldg(forgetting_factor);
        float p = 1.f;
        const int e = (CHARS - 1) - t;
        for (int i = 0; i < e; ++i) p *= alpha;
        pw_s[t] = p;
    }
    __syncthreads();

    // Phase B: scatter 16 rows * 20 chars = 320 smem atomics (ATOMS spread)
    {
        const int r  = t / CHARS;
        const int k  = t - r * CHARS;
        const int id = __ldg(char_ids + (size_t)(row0 + r) * CHARS + k);
        atomicAdd(&hist[r * VOCAB + id], pw_s[k]);
        const int t2 = t + THREADS;            // tasks 256..319 on threads 0..63
        if (t2 < TASKS) {
            const int r2  = t2 / CHARS;
            const int k2  = t2 - r2 * CHARS;
            const int id2 = __ldg(char_ids + (size_t)(row0 + r2) * CHARS + k2);
            atomicAdd(&hist[r2 * VOCAB + id2], pw_s[k2]);
        }
    }
    __syncthreads();

    // Order generic-proxy smem writes before the async-proxy TMA read
    asm volatile("fence.proxy.async.shared::cta;" ::: "memory");

    // Phase C: bulk TMA store smem -> global (bypasses L1/LSU entirely)
    if (t == 0) {
        const uint32_t src = smem_u32(hist);
        asm volatile(
            "cp.async.bulk.global.shared::cta.bulk_group [%0], [%1], %2;"
            :: "l"(block_out), "r"(src), "n"(HIST_BYTES) : "memory");
        asm volatile("cp.async.bulk.commit_group;" ::: "memory");
        asm volatile("cp.async.bulk.wait_group 0;" ::: "memory");
    }
}

extern "C" void kernel_launch(void* const* d_in, const int* in_sizes, int n_in,
                              void* d_out, int out_size) {
    const int* char_ids;
    const float* ff;
    if (in_sizes[0] > in_sizes[1]) {
        char_ids = (const int*)d_in[0];
        ff = (const float*)d_in[1];
    } else {
        char_ids = (const int*)d_in[1];
        ff = (const float*)d_in[0];
    }
    float* out = (float*)d_out;

    const int n_rows   = out_size / VOCAB;             // 131072
    const int n_blocks = n_rows / ROWS_PER_BLOCK;      // 8192

    fofe_tma_kernel<<<n_blocks, THREADS>>>(char_ids, ff, out);
}